// round 16
// baseline (speedup 1.0000x reference)
#include <cuda_runtime.h>
#include <cuda_bf16.h>
#include <cuda_fp16.h>
#include <cstdint>

namespace {
constexpr int P_     = 256;
constexpr int H_     = 32;
constexpr int DM     = 2048;
constexpr int HD     = 64;
constexpr int PATCH_ = 256;

constexpr int BM = 64;
constexpr int BN = 64;
constexpr int KC = 64;                  // k per smem stage
constexpr int N_TILES  = DM / KC;       // gemm_out: 32 stages
constexpr int NV_TILES = PATCH_ / KC;   // gemm_v:   4 stages
constexpr int NC_TILES = P_ / KC;       // circ_att: 4 stages
constexpr int PANEL = BM * 144;         // 64 rows x 144B = 9216 B

// gemm_out: Y16r, Y16i + 3 chains x (Wh, Wl) = 8 panels / stage, depth-3
constexpr int STAGE = 8 * PANEL;        // 73728 B
constexpr int SMEM_GEMM = 3 * STAGE;    // 221184 B
// gemm_v (BM=32): X_hi, X_lo (32-row) + 4 V panels (64-row); depth-4
constexpr int BMV     = 32;
constexpr int APANELV = BMV * 144;      // 4608 B
constexpr int VSTAGE  = 2 * APANELV + 4 * PANEL;  // 46080 B
constexpr int SMEM_V  = 4 * VSTAGE;     // 184320 B
// circ_att: 3 chains x (B_hi, B_lo) = 6 panels + pair tables
constexpr int CSTAGE = 6 * PANEL;       // 55296 B
constexpr int SMEM_C = 2 * CSTAGE + 6 * 512 * 4;  // 122880 B

constexpr float WSCALE   = 64.0f;
constexpr float WSCALE_I = 1.0f / 64.0f;
}

// ------------------------- device scratch (static) -------------------------
__device__ __nv_bfloat16 g_X_hi[P_ * PATCH_];
__device__ __nv_bfloat16 g_X_lo[P_ * PATCH_];
__device__ __nv_bfloat16 g_VtR_hi[DM * PATCH_];   // [n][k] = vR_k[k][n]
__device__ __nv_bfloat16 g_VtR_lo[DM * PATCH_];
__device__ __nv_bfloat16 g_VtI_hi[DM * PATCH_];
__device__ __nv_bfloat16 g_VtI_lo[DM * PATCH_];

// v panels in natural [q][DM] layout (written by gemm_v_mma epilogue)
__device__ __nv_bfloat16 g_vr_hi[P_ * DM];
__device__ __nv_bfloat16 g_vr_lo[P_ * DM];
__device__ __nv_bfloat16 g_vi_hi[P_ * DM];
__device__ __nv_bfloat16 g_vi_lo[P_ * DM];
__device__ __nv_bfloat16 g_vs_hi[P_ * DM];
__device__ __nv_bfloat16 g_vs_lo[P_ * DM];

// Y panels as single fp16 (A operand of fp16 2-term gemm_out)
__device__ __half g_Y16r[P_ * DM];
__device__ __half g_Y16i[P_ * DM];

// W panels: (w * 64) split into fp16 hi/lo, [n][k] layout
__device__ __half g_W16R_h[DM * DM];
__device__ __half g_W16R_l[DM * DM];
__device__ __half g_W16I_h[DM * DM];
__device__ __half g_W16I_l[DM * DM];
__device__ __half g_W16S_h[DM * DM];
__device__ __half g_W16S_l[DM * DM];

__device__ __forceinline__ int clampi(int i, int sz) { return i < sz ? i : sz - 1; }

// ------------------------- asm helpers -------------------------
__device__ __forceinline__ uint32_t smem_u32(const void* p) {
    uint32_t a;
    asm("{ .reg .u64 t; cvta.to.shared.u64 t, %1; cvt.u32.u64 %0, t; }"
        : "=r"(a) : "l"(p));
    return a;
}
__device__ __forceinline__ void cpasync16(uint32_t s, const void* g) {
    asm volatile("cp.async.cg.shared.global [%0], [%1], 16;" :: "r"(s), "l"(g));
}
__device__ __forceinline__ void cp_commit() { asm volatile("cp.async.commit_group;"); }
__device__ __forceinline__ void cp_wait1()  { asm volatile("cp.async.wait_group 1;"); }
__device__ __forceinline__ void cp_wait0()  { asm volatile("cp.async.wait_group 0;"); }
template <int N>
__device__ __forceinline__ void cp_waitn() {
    asm volatile("cp.async.wait_group %0;" :: "n"(N));
}
__device__ __forceinline__ void ldmx4(uint32_t* r, uint32_t addr) {
    asm volatile("ldmatrix.sync.aligned.m8n8.x4.shared.b16 {%0,%1,%2,%3}, [%4];"
                 : "=r"(r[0]), "=r"(r[1]), "=r"(r[2]), "=r"(r[3]) : "r"(addr));
}
__device__ __forceinline__ void ldmx4t(uint32_t* r, uint32_t addr) {
    asm volatile("ldmatrix.sync.aligned.m8n8.x4.trans.shared.b16 {%0,%1,%2,%3}, [%4];"
                 : "=r"(r[0]), "=r"(r[1]), "=r"(r[2]), "=r"(r[3]) : "r"(addr));
}
__device__ __forceinline__ uint32_t hadd2u(uint32_t a, uint32_t b) {
    uint32_t r;
    asm("add.rn.f16x2 %0, %1, %2;" : "=r"(r) : "r"(a), "r"(b));
    return r;
}
#define MMA_BF16(d, a, b0_, b1_)                                               \
    asm volatile(                                                              \
        "mma.sync.aligned.m16n8k16.row.col.f32.bf16.bf16.f32 "                 \
        "{%0,%1,%2,%3}, {%4,%5,%6,%7}, {%8,%9}, {%0,%1,%2,%3};"                \
        : "+f"(d[0]), "+f"(d[1]), "+f"(d[2]), "+f"(d[3])                       \
        : "r"(a[0]), "r"(a[1]), "r"(a[2]), "r"(a[3]), "r"(b0_), "r"(b1_))
#define MMA_F16(d, a, b0_, b1_)                                                \
    asm volatile(                                                              \
        "mma.sync.aligned.m16n8k16.row.col.f32.f16.f16.f32 "                   \
        "{%0,%1,%2,%3}, {%4,%5,%6,%7}, {%8,%9}, {%0,%1,%2,%3};"                \
        : "+f"(d[0]), "+f"(d[1]), "+f"(d[2]), "+f"(d[3])                       \
        : "r"(a[0]), "r"(a[1]), "r"(a[2]), "r"(a[3]), "r"(b0_), "r"(b1_))

__device__ __forceinline__ uint16_t bf_bits(__nv_bfloat16 h) {
    return *reinterpret_cast<uint16_t*>(&h);
}
__device__ __forceinline__ void store_split2(__nv_bfloat16* hi, __nv_bfloat16* lo,
                                             int oi, float a, float b) {
    __nv_bfloat16 h0 = __float2bfloat16(a);
    __nv_bfloat16 h1 = __float2bfloat16(b);
    *(__nv_bfloat162*)&hi[oi] = __nv_bfloat162(h0, h1);
    *(__nv_bfloat162*)&lo[oi] = __nv_bfloat162(
        __float2bfloat16(a - __bfloat162float(h0)),
        __float2bfloat16(b - __bfloat162float(h1)));
}
__device__ __forceinline__ void store_split2h(__half* hi, __half* lo,
                                              int oi, float a, float b) {
    __half h0 = __float2half_rn(a);
    __half h1 = __float2half_rn(b);
    *(__half2*)&hi[oi] = __halves2half2(h0, h1);
    *(__half2*)&lo[oi] = __halves2half2(
        __float2half_rn(a - __half2float(h0)),
        __float2half_rn(b - __half2float(h1)));
}

// ---------------------------------------------------------------------------
// Kernel 0a: split x into bf16 hi/lo
// ---------------------------------------------------------------------------
__global__ void split_x(const float* __restrict__ x, int sx)
{
    int i = blockIdx.x * 256 + threadIdx.x;
    if (i >= P_ * PATCH_) return;
    float a = x[clampi(i, sx)];
    __nv_bfloat16 h = __float2bfloat16(a);
    g_X_hi[i] = h;
    g_X_lo[i] = __float2bfloat16(a - __bfloat162float(h));
}

// ---------------------------------------------------------------------------
// Kernel 0b: transpose + split vR_k, vI_k -> 4 bf16 panels [n][k]
// ---------------------------------------------------------------------------
__global__ void split_vk(const float* __restrict__ VR,
                         const float* __restrict__ VI, int sv)
{
    __shared__ float tR[32][33];
    __shared__ float tI[32][33];
    const int tid = threadIdx.x;
    const int n0 = blockIdx.x * 32, k0 = blockIdx.y * 32;

    #pragma unroll
    for (int i = 0; i < 4; i++) {
        int idx = tid + i * 256;
        int kk = idx >> 5, nn = idx & 31;
        int gi = clampi((k0 + kk) * DM + n0 + nn, sv);
        tR[nn][kk] = VR[gi];
        tI[nn][kk] = VI[gi];
    }
    __syncthreads();

    const int kp  = tid & 15;
    const int nn2 = tid >> 4;
    #pragma unroll
    for (int half = 0; half < 2; half++) {
        int n = nn2 + half * 16;
        int k = kp * 2;
        int oi = (n0 + n) * PATCH_ + k0 + k;
        store_split2(g_VtR_hi, g_VtR_lo, oi, tR[n][k], tR[n][k + 1]);
        store_split2(g_VtI_hi, g_VtI_lo, oi, tI[n][k], tI[n][k + 1]);
    }
}

// ---------------------------------------------------------------------------
// Kernel 1: gemm_v via mma.sync, FUSED 3-term split, DEPTH-4 pipeline.
// Retiled BM=32 -> grid (32, 8) = 256 CTAs; warp tile 16x16 (wm2 x wn4).
// ---------------------------------------------------------------------------
__global__ void __launch_bounds__(256)
gemm_v_mma(const float* __restrict__ br, const float* __restrict__ bi, int sb)
{
    extern __shared__ __align__(16) char smem[];
    const uint32_t sbase = smem_u32(smem);

    const int tid  = threadIdx.x;
    const int lane = tid & 31, wid = tid >> 5;
    const int g    = lane >> 2, tig = lane & 3;
    const int wm   = wid >> 2, wn = wid & 3;
    const int m0   = blockIdx.y * BMV, n0 = blockIdx.x * BN;

    const int a_row_off = (lane & 7) + ((lane >> 3) & 1) * 8;
    const int a_col_off = (lane >> 4) * 8;
    const int b_row_off = (lane & 7) + (lane >> 4) * 8;
    const int b_col_off = ((lane >> 3) & 1) * 8;

    float acc[2][2][4] = {};   // [chain][nn][c]

    // cp.async A panels (32 rows x 8 chunks = 256): one chunk per thread
    const int a_row = tid >> 3, a_q = tid & 7;
    // cp.async B panels (64 rows x 8 chunks = 512): two chunks per thread
    const int ch_row0 = tid >> 2;
    const int ch_q0   = (tid & 3);
    const int ch_q1   = (tid & 3) + 4;

    // panel offsets: A0 @0, A1 @4608, B0..B3 @9216 + i*9216
    auto issue_stage = [&](int t) {
        const int k0 = t * KC;
        const uint32_t sb_ = sbase + t * VSTAGE;
        {
            const __nv_bfloat16* gp = g_X_hi + (m0 + a_row) * PATCH_ + k0;
            cpasync16(sb_ + a_row * 144 + a_q * 16, gp + a_q * 8);
            const __nv_bfloat16* gq = g_X_lo + (m0 + a_row) * PATCH_ + k0;
            cpasync16(sb_ + APANELV + a_row * 144 + a_q * 16, gq + a_q * 8);
        }
        const __nv_bfloat16* Bp[4] = {g_VtR_hi, g_VtR_lo, g_VtI_hi, g_VtI_lo};
        #pragma unroll
        for (int p = 0; p < 4; p++) {
            const __nv_bfloat16* gb = Bp[p] + (n0 + ch_row0) * PATCH_ + k0;
            uint32_t sa = sb_ + 2 * APANELV + p * PANEL + ch_row0 * 144;
            cpasync16(sa + ch_q0 * 16, gb + ch_q0 * 8);
            cpasync16(sa + ch_q1 * 16, gb + ch_q1 * 8);
        }
        cp_commit();
    };

    issue_stage(0);
    issue_stage(1);
    issue_stage(2);
    issue_stage(3);

    #pragma unroll
    for (int t = 0; t < NV_TILES; t++) {
        if      (t == 0) cp_waitn<3>();
        else if (t == 1) cp_waitn<2>();
        else if (t == 2) cp_waitn<1>();
        else             cp_waitn<0>();
        __syncthreads();

        const uint32_t base = sbase + t * VSTAGE;
        const int r0 = wm * 16;
        #pragma unroll
        for (int kk = 0; kk < KC; kk += 16) {
            uint32_t ah[4], al[4];
            ldmx4(ah, base + (r0 + a_row_off) * 144 + (kk + a_col_off) * 2);
            ldmx4(al, base + APANELV + (r0 + a_row_off) * 144 + (kk + a_col_off) * 2);
            #pragma unroll
            for (int c = 0; c < 2; c++) {
                uint32_t bh[4], bl[4];
                int nr = wn * 16;
                ldmx4(bh, base + 2 * APANELV + (c * 2 + 0) * PANEL +
                          (nr + b_row_off) * 144 + (kk + b_col_off) * 2);
                ldmx4(bl, base + 2 * APANELV + (c * 2 + 1) * PANEL +
                          (nr + b_row_off) * 144 + (kk + b_col_off) * 2);
                #pragma unroll
                for (int nn = 0; nn < 2; nn++) {
                    MMA_BF16(acc[c][nn], ah, bh[nn * 2], bh[nn * 2 + 1]);
                    MMA_BF16(acc[c][nn], ah, bl[nn * 2], bl[nn * 2 + 1]);
                    MMA_BF16(acc[c][nn], al, bh[nn * 2], bh[nn * 2 + 1]);
                }
            }
        }
    }

    // fused epilogue: bias + hi/lo split of vr, vi, vs = vr+vi
    #pragma unroll
    for (int nn = 0; nn < 2; nn++) {
        int mi = m0 + wm * 16 + g;
        int ni = n0 + wn * 16 + nn * 8 + tig * 2;
        float b0r = br[clampi(ni, sb)],     b1r = br[clampi(ni + 1, sb)];
        float b0i = bi[clampi(ni, sb)],     b1i = bi[clampi(ni + 1, sb)];
        #pragma unroll
        for (int half = 0; half < 2; half++) {
            int m = mi + half * 8;
            float vr0 = acc[0][nn][half * 2]     + b0r;
            float vr1 = acc[0][nn][half * 2 + 1] + b1r;
            float vi0 = acc[1][nn][half * 2]     + b0i;
            float vi1 = acc[1][nn][half * 2 + 1] + b1i;
            float vs0 = vr0 + vi0, vs1 = vr1 + vi1;
            int oi = m * DM + ni;
            store_split2(g_vr_hi, g_vr_lo, oi, vr0, vr1);
            store_split2(g_vi_hi, g_vi_lo, oi, vi0, vi1);
            store_split2(g_vs_hi, g_vs_lo, oi, vs0, vs1);
        }
    }
}

// ---------------------------------------------------------------------------
// Kernel 2: circulant attention via mma.sync, FUSED split (single K sweep).
// Epilogue writes Y as fp16 panels (Y16r, Y16i only; Ys synthesized later).
// ---------------------------------------------------------------------------
__global__ void __launch_bounds__(256)
circ_att_mma(const float* __restrict__ JR, const float* __restrict__ JI, int sj)
{
    extern __shared__ __align__(16) char smem[];
    const uint32_t sbase = smem_u32(smem);
    uint32_t* pair = (uint32_t*)(smem + 2 * CSTAGE);   // [6][512]

    const int tid  = threadIdx.x;
    const int lane = tid & 31, wid = tid >> 5;
    const int g    = lane >> 2, tig = lane & 3;
    const int wm   = wid >> 2, wn = wid & 3;
    const int h    = blockIdx.y;
    const int s0   = blockIdx.x * 64;

    const int bt_row = (lane & 7) + ((lane >> 3) & 1) * 8;
    const int bt_col = (lane >> 4) * 8;

    for (int t = tid; t < 512; t += 256) {
        float jr0 = JR[clampi(((t) & 255) * H_ + h, sj)];
        float jr1 = JR[clampi(((t + 1) & 255) * H_ + h, sj)];
        float ji0 = JI[clampi(((t) & 255) * H_ + h, sj)];
        float ji1 = JI[clampi(((t + 1) & 255) * H_ + h, sj)];
        float v0[3] = {jr0, ji0, jr0 + ji0};
        float v1[3] = {jr1, ji1, jr1 + ji1};
        #pragma unroll
        for (int c = 0; c < 3; c++) {
            __nv_bfloat16 h0 = __float2bfloat16(v0[c]);
            __nv_bfloat16 h1 = __float2bfloat16(v1[c]);
            __nv_bfloat16 l0 = __float2bfloat16(v0[c] - __bfloat162float(h0));
            __nv_bfloat16 l1 = __float2bfloat16(v1[c] - __bfloat162float(h1));
            pair[(c * 2 + 0) * 512 + t] =
                (uint32_t)bf_bits(h0) | ((uint32_t)bf_bits(h1) << 16);
            pair[(c * 2 + 1) * 512 + t] =
                (uint32_t)bf_bits(l0) | ((uint32_t)bf_bits(l1) << 16);
        }
    }

    float acc[3][2][2][4] = {};

    const int ch_row0 = tid >> 2;
    const int ch_q0   = (tid & 3);
    const int ch_q1   = (tid & 3) + 4;

    auto issue_stage = [&](int t) {
        const int k0 = t * KC;
        const __nv_bfloat16* Gp[6] = {g_vr_hi, g_vr_lo, g_vi_hi, g_vi_lo,
                                      g_vs_hi, g_vs_lo};
        const uint32_t sb_ = sbase + (t & 1) * CSTAGE;
        #pragma unroll
        for (int p = 0; p < 6; p++) {
            const __nv_bfloat16* gb = Gp[p] + (k0 + ch_row0) * DM + h * HD;
            uint32_t s = sb_ + p * PANEL + ch_row0 * 144;
            cpasync16(s + ch_q0 * 16, gb + ch_q0 * 8);
            cpasync16(s + ch_q1 * 16, gb + ch_q1 * 8);
        }
        cp_commit();
    };

    __syncthreads();
    issue_stage(0);

    for (int t = 0; t < NC_TILES; t++) {
        const int s = t & 1;
        if (t + 1 < NC_TILES) { issue_stage(t + 1); cp_wait1(); }
        else                  { cp_wait0(); }
        __syncthreads();

        const uint32_t base = sbase + s * CSTAGE;
        #pragma unroll
        for (int kk = 0; kk < KC; kk += 16) {
            const int tbase = s0 + wm * 32 + g + t * 64 + kk + tig * 2;
            #pragma unroll
            for (int c = 0; c < 3; c++) {
                const uint32_t* Ph = &pair[(c * 2 + 0) * 512];
                const uint32_t* Pl = &pair[(c * 2 + 1) * 512];
                uint32_t h0 = Ph[tbase],      h1 = Ph[tbase + 8];
                uint32_t h2 = Ph[tbase + 16], h3 = Ph[tbase + 24];
                uint32_t h4 = Ph[tbase + 32];
                uint32_t l0 = Pl[tbase],      l1 = Pl[tbase + 8];
                uint32_t l2 = Pl[tbase + 16], l3 = Pl[tbase + 24];
                uint32_t l4 = Pl[tbase + 32];
                uint32_t ah0[4] = {h0, h1, h1, h2};
                uint32_t ah1[4] = {h2, h3, h3, h4};
                uint32_t al0[4] = {l0, l1, l1, l2};
                uint32_t al1[4] = {l2, l3, l3, l4};
                uint32_t bh[4], bl[4];
                ldmx4t(bh, base + (c * 2 + 0) * PANEL +
                           (kk + bt_row) * 144 + (wn * 16 + bt_col) * 2);
                ldmx4t(bl, base + (c * 2 + 1) * PANEL +
                           (kk + bt_row) * 144 + (wn * 16 + bt_col) * 2);
                MMA_BF16(acc[c][0][0], ah0, bh[0], bh[1]);
                MMA_BF16(acc[c][0][1], ah0, bh[2], bh[3]);
                MMA_BF16(acc[c][1][0], ah1, bh[0], bh[1]);
                MMA_BF16(acc[c][1][1], ah1, bh[2], bh[3]);
                MMA_BF16(acc[c][0][0], ah0, bl[0], bl[1]);
                MMA_BF16(acc[c][0][1], ah0, bl[2], bl[3]);
                MMA_BF16(acc[c][1][0], ah1, bl[0], bl[1]);
                MMA_BF16(acc[c][1][1], ah1, bl[2], bl[3]);
                MMA_BF16(acc[c][0][0], al0, bh[0], bh[1]);
                MMA_BF16(acc[c][0][1], al0, bh[2], bh[3]);
                MMA_BF16(acc[c][1][0], al1, bh[0], bh[1]);
                MMA_BF16(acc[c][1][1], al1, bh[2], bh[3]);
            }
        }
        __syncthreads();
    }

    // epilogue: Karatsuba combine + fp16 write of Y16r / Y16i
    #pragma unroll
    for (int mm = 0; mm < 2; mm++) {
        #pragma unroll
        for (int nn = 0; nn < 2; nn++) {
            #pragma unroll
            for (int c2 = 0; c2 < 4; c2++) {
                int m = s0 + wm * 32 + mm * 16 + g + (c2 >> 1) * 8;
                int n = h * HD + wn * 16 + nn * 8 + tig * 2 + (c2 & 1);
                float C1 = acc[0][mm][nn][c2];
                float C2 = acc[1][mm][nn][c2];
                float C3 = acc[2][mm][nn][c2];
                float a  = C1 - C2;
                float b  = C3 - C1 - C2;
                int idx = m * DM + n;
                g_Y16r[idx] = __float2half_rn(a);
                g_Y16i[idx] = __float2half_rn(b);
            }
        }
    }
}

// ---------------------------------------------------------------------------
// Kernel 3: transpose + scale(x64) + fp16 hi/lo split of WR, WI, WR+WI
// ---------------------------------------------------------------------------
__global__ void split_wt(const float* __restrict__ WR,
                         const float* __restrict__ WI, int sw)
{
    __shared__ float tR[32][33];
    __shared__ float tI[32][33];
    const int tid = threadIdx.x;
    const int n0 = blockIdx.x * 32, k0 = blockIdx.y * 32;

    #pragma unroll
    for (int i = 0; i < 4; i++) {
        int idx = tid + i * 256;
        int kk = idx >> 5, nn = idx & 31;
        int gi = clampi((k0 + kk) * DM + n0 + nn, sw);
        tR[nn][kk] = WR[gi];
        tI[nn][kk] = WI[gi];
    }
    __syncthreads();

    const int kp  = tid & 15;
    const int nn2 = tid >> 4;
    #pragma unroll
    for (int half = 0; half < 2; half++) {
        int n = nn2 + half * 16;
        int k = kp * 2;
        float r0 = tR[n][k] * WSCALE,     r1 = tR[n][k + 1] * WSCALE;
        float i0 = tI[n][k] * WSCALE,     i1 = tI[n][k + 1] * WSCALE;
        int oi = (n0 + n) * DM + k0 + k;
        store_split2h(g_W16R_h, g_W16R_l, oi, r0, r1);
        store_split2h(g_W16I_h, g_W16I_l, oi, i0, i1);
        store_split2h(g_W16S_h, g_W16S_l, oi, r0 + i0, r1 + i1);
    }
}

// ---------------------------------------------------------------------------
// Kernel 4: Karatsuba fp16 2-TERM GEMM, DEPTH-3, Ys synthesized via add.f16x2.
//   8 panels/stage: Y16r, Y16i, WRh, WRl, WIh, WIl, WSh, WSl.
// ---------------------------------------------------------------------------
__global__ void __launch_bounds__(256)
gemm_out_mma(const float* __restrict__ bR, const float* __restrict__ bI, int sb,
             float* __restrict__ out, int out_floats, int mode)
{
    extern __shared__ __align__(16) char smem[];
    const uint32_t sbase = smem_u32(smem);

    const int tid  = threadIdx.x;
    const int lane = tid & 31, wid = tid >> 5;
    const int g    = lane >> 2, tig = lane & 3;
    const int wm   = wid >> 2, wn = wid & 3;
    const int m0   = blockIdx.y * BM, n0 = blockIdx.x * BN;

    const int a_row_off = (lane & 7) + ((lane >> 3) & 1) * 8;
    const int a_col_off = (lane >> 4) * 8;
    const int b_row_off = (lane & 7) + (lane >> 4) * 8;
    const int b_col_off = ((lane >> 3) & 1) * 8;

    float acc[3][2][2][4] = {};

    const int ch_row0 = tid >> 2;
    const int ch_q0   = (tid & 3);
    const int ch_q1   = (tid & 3) + 4;

    // panels: 0 Y16r, 1 Y16i, 2 WRh, 3 WRl, 4 WIh, 5 WIl, 6 WSh, 7 WSl
    auto issue_stage = [&](int t) {
        const int k0 = t * KC;
        const __half* Gp[8] = {g_Y16r, g_Y16i,
                               g_W16R_h, g_W16R_l, g_W16I_h, g_W16I_l,
                               g_W16S_h, g_W16S_l};
        const uint32_t sb_ = sbase + (t % 3) * STAGE;
        #pragma unroll
        for (int p = 0; p < 8; p++) {
            const int rowbase = (p < 2) ? m0 : n0;
            const __half* gp = Gp[p] + (rowbase + ch_row0) * DM + k0;
            uint32_t sa = sb_ + p * PANEL + ch_row0 * 144;
            cpasync16(sa + ch_q0 * 16, gp + ch_q0 * 8);
            cpasync16(sa + ch_q1 * 16, gp + ch_q1 * 8);
        }
        cp_commit();
    };

    issue_stage(0);
    issue_stage(1);

    for (int t = 0; t < N_TILES; t++) {
        if (t + 2 < N_TILES)      { issue_stage(t + 2); cp_waitn<2>(); }
        else if (t + 1 < N_TILES) { cp_waitn<1>(); }
        else                      { cp_waitn<0>(); }
        __syncthreads();

        const uint32_t base = sbase + (t % 3) * STAGE;
        #pragma unroll
        for (int kk = 0; kk < KC; kk += 16) {
            uint32_t ar[2][4], ai[2][4], as_[2][4];
            #pragma unroll
            for (int mm = 0; mm < 2; mm++) {
                int r0 = wm * 32 + mm * 16;
                ldmx4(ar[mm], base + 0 * PANEL +
                              (r0 + a_row_off) * 144 + (kk + a_col_off) * 2);
                ldmx4(ai[mm], base + 1 * PANEL +
                              (r0 + a_row_off) * 144 + (kk + a_col_off) * 2);
                #pragma unroll
                for (int j = 0; j < 4; j++)
                    as_[mm][j] = hadd2u(ar[mm][j], ai[mm][j]);
            }
            #pragma unroll
            for (int c = 0; c < 3; c++) {
                uint32_t (*a)[4] = (c == 0) ? ar : (c == 1) ? ai : as_;
                uint32_t bh[4], bl[4];
                {
                    int nr = wn * 16;
                    ldmx4(bh, base + (2 + c * 2) * PANEL +
                              (nr + b_row_off) * 144 + (kk + b_col_off) * 2);
                    ldmx4(bl, base + (3 + c * 2) * PANEL +
                              (nr + b_row_off) * 144 + (kk + b_col_off) * 2);
                }
                #pragma unroll
                for (int mm = 0; mm < 2; mm++)
                    #pragma unroll
                    for (int nn = 0; nn < 2; nn++) {
                        MMA_F16(acc[c][mm][nn], a[mm], bh[nn * 2], bh[nn * 2 + 1]);
                        MMA_F16(acc[c][mm][nn], a[mm], bl[nn * 2], bl[nn * 2 + 1]);
                    }
            }
        }
        __syncthreads();
    }

    const float LN2 = 0.69314718055994531f;
    #pragma unroll
    for (int mm = 0; mm < 2; mm++) {
        #pragma unroll
        for (int nn = 0; nn < 2; nn++) {
            int mi = m0 + wm * 32 + mm * 16 + g;
            int ni = n0 + wn * 16 + nn * 8 + tig * 2;
            #pragma unroll
            for (int c = 0; c < 4; c++) {
                int m = mi + (c >> 1) * 8;
                int n = ni + (c & 1);
                float C1 = acc[0][mm][nn][c];
                float C2 = acc[1][mm][nn][c];
                float C3 = acc[2][mm][nn][c];
                float re = (C1 - C2) * WSCALE_I + bR[clampi(n, sb)];
                float im = (C3 - C1 - C2) * WSCALE_I + bI[clampi(n, sb)];
                float sgn = (__float_as_int(re) < 0) ? -1.0f : 1.0f;
                float a = re * sgn;
                float b = im * sgn;
                float e = __expf(-2.0f * a);
                float s2, c2;
                __sincosf(2.0f * b, &s2, &c2);
                float wr = e * c2, wi = -e * s2;
                float u = 1.0f + wr;
                float res_re = a + 0.5f * __logf(u * u + wi * wi) - LN2;
                if (mode == 0) {
                    int fi = m * DM + n;
                    if (fi < out_floats) out[fi] = res_re;
                } else {
                    float res_im = b + atan2f(wi, u);
                    int fi = (m * DM + n) * 2;
                    if (fi < out_floats)     out[fi]     = res_re;
                    if (fi + 1 < out_floats) out[fi + 1] = res_im;
                }
            }
        }
    }
}

// ---------------------------------------------------------------------------
extern "C" void kernel_launch(void* const* d_in, const int* in_sizes, int n_in,
                              void* d_out, int out_size)
{
    const float* x = nullptr;   int sx = 0;
    const float* vk[2] = {};    int svk = 0;
    const float* J[2]  = {};    int sj = 0;
    const float* wk[2] = {};    int swk = 0;
    const float* bs[4] = {};    int sb = 0;
    int nvk = 0, nj = 0, nwk = 0, nb = 0;

    for (int i = 0; i < n_in; i++) {
        const float* p = (const float*)d_in[i];
        int sz = in_sizes[i];
        if      (sz == 65536   && !x)      { x = p; sx = sz; }
        else if (sz == 524288  && nvk < 2) { vk[nvk++] = p; svk = sz; }
        else if (sz == 8192    && nj  < 2) { J[nj++]   = p; sj  = sz; }
        else if (sz == 4194304 && nwk < 2) { wk[nwk++] = p; swk = sz; }
        else if (sz == 2048    && nb  < 4) { bs[nb++]  = p; sb  = sz; }
    }

    if (!(x && nvk == 2 && nj == 2 && nwk == 2 && nb == 4)) {
        if (n_in < 11) return;
        x     = (const float*)d_in[0];  sx  = in_sizes[0];
        vk[0] = (const float*)d_in[1];  bs[0] = (const float*)d_in[2];
        vk[1] = (const float*)d_in[3];  bs[1] = (const float*)d_in[4];
        J[0]  = (const float*)d_in[5];  J[1]  = (const float*)d_in[6];
        wk[0] = (const float*)d_in[7];  bs[2] = (const float*)d_in[8];
        wk[1] = (const float*)d_in[9];  bs[3] = (const float*)d_in[10];
        svk = in_sizes[1]; sj = in_sizes[5]; swk = in_sizes[7]; sb = in_sizes[2];
    }

    int mode       = (out_size == 2 * P_ * DM) ? 1 : 0;
    int out_floats = out_size;

    static bool attr_done = false;
    static cudaStream_t s_side = nullptr;
    static cudaEvent_t ev_fork = nullptr, ev_join = nullptr;
    if (!attr_done) {
        cudaFuncSetAttribute(gemm_out_mma,
                             cudaFuncAttributeMaxDynamicSharedMemorySize, SMEM_GEMM);
        cudaFuncSetAttribute(gemm_v_mma,
                             cudaFuncAttributeMaxDynamicSharedMemorySize, SMEM_V);
        cudaFuncSetAttribute(circ_att_mma,
                             cudaFuncAttributeMaxDynamicSharedMemorySize, SMEM_C);
        cudaStreamCreateWithFlags(&s_side, cudaStreamNonBlocking);
        cudaEventCreateWithFlags(&ev_fork, cudaEventDisableTiming);
        cudaEventCreateWithFlags(&ev_join, cudaEventDisableTiming);
        attr_done = true;
    }

    // fork: split_wt (independent of the v/att chain) runs on side stream
    cudaEventRecord(ev_fork, 0);
    cudaStreamWaitEvent(s_side, ev_fork, 0);
    split_wt<<<dim3(DM / 32, DM / 32), 256, 0, s_side>>>(wk[0], wk[1], swk);
    cudaEventRecord(ev_join, s_side);

    // main chain (default stream)
    split_x   <<<(P_ * PATCH_ + 255) / 256, 256>>>(x, sx);
    split_vk  <<<dim3(DM / 32, PATCH_ / 32), 256>>>(vk[0], vk[1], svk);
    gemm_v_mma<<<dim3(DM / BN, P_ / BMV), 256, SMEM_V>>>(bs[0], bs[1], sb);
    circ_att_mma<<<dim3(P_ / 64, H_), 256, SMEM_C>>>(J[0], J[1], sj);

    // join: gemm_out needs both Y panels (chain) and W panels (side)
    cudaStreamWaitEvent(0, ev_join, 0);
    gemm_out_mma<<<dim3(DM / BN, P_ / BM), 256, SMEM_GEMM>>>(
        bs[2], bs[3], sb, (float*)d_out, out_floats, mode);
}

// round 17
// speedup vs baseline: 1.4311x; 1.4311x over previous
#include <cuda_runtime.h>
#include <cuda_bf16.h>
#include <cuda_fp16.h>
#include <cstdint>

namespace {
constexpr int P_     = 256;
constexpr int H_     = 32;
constexpr int DM     = 2048;
constexpr int HD     = 64;
constexpr int PATCH_ = 256;

constexpr int BM = 64;
constexpr int BN = 64;
constexpr int KC = 64;                  // k per smem stage
constexpr int N_TILES  = DM / KC;       // gemm_out: 32 stages
constexpr int NV_TILES = PATCH_ / KC;   // gemm_v:   4 stages
constexpr int NC_TILES = P_ / KC;       // circ_att: 4 stages
constexpr int PANEL = BM * 144;         // 64 rows x 144B = 9216 B

// gemm_out: 3 chains x (Y16, Wh, Wl) = 9 panels / stage (fp16 2-term)
constexpr int STAGE = 9 * PANEL;        // 82944 B
constexpr int SMEM_GEMM = 2 * STAGE;    // 165888 B
// gemm_v: X_hi, X_lo, VtR_hi, VtR_lo, VtI_hi, VtI_lo = 6 panels; depth-4
constexpr int VSTAGE = 6 * PANEL;       // 55296 B
constexpr int SMEM_V  = 4 * VSTAGE;     // 221184 B
// circ_att: 3 chains x (B_hi, B_lo) = 6 panels + pair tables
constexpr int CSTAGE = 6 * PANEL;       // 55296 B
constexpr int SMEM_C = 2 * CSTAGE + 6 * 512 * 4;  // 122880 B

constexpr float WSCALE   = 64.0f;
constexpr float WSCALE_I = 1.0f / 64.0f;
}

// ------------------------- device scratch (static) -------------------------
__device__ __nv_bfloat16 g_X_hi[P_ * PATCH_];
__device__ __nv_bfloat16 g_X_lo[P_ * PATCH_];
__device__ __nv_bfloat16 g_VtR_hi[DM * PATCH_];   // [n][k] = vR_k[k][n]
__device__ __nv_bfloat16 g_VtR_lo[DM * PATCH_];
__device__ __nv_bfloat16 g_VtI_hi[DM * PATCH_];
__device__ __nv_bfloat16 g_VtI_lo[DM * PATCH_];

// v panels in natural [q][DM] layout (written by gemm_v_mma epilogue)
__device__ __nv_bfloat16 g_vr_hi[P_ * DM];
__device__ __nv_bfloat16 g_vr_lo[P_ * DM];
__device__ __nv_bfloat16 g_vi_hi[P_ * DM];
__device__ __nv_bfloat16 g_vi_lo[P_ * DM];
__device__ __nv_bfloat16 g_vs_hi[P_ * DM];
__device__ __nv_bfloat16 g_vs_lo[P_ * DM];

// Y panels as single fp16 (A operand of fp16 2-term gemm_out)
__device__ __half g_Y16r[P_ * DM];
__device__ __half g_Y16i[P_ * DM];
__device__ __half g_Y16s[P_ * DM];

// W panels: (w * 64) split into fp16 hi/lo, [n][k] layout
__device__ __half g_W16R_h[DM * DM];
__device__ __half g_W16R_l[DM * DM];
__device__ __half g_W16I_h[DM * DM];
__device__ __half g_W16I_l[DM * DM];
__device__ __half g_W16S_h[DM * DM];
__device__ __half g_W16S_l[DM * DM];

__device__ __forceinline__ int clampi(int i, int sz) { return i < sz ? i : sz - 1; }

// ------------------------- asm helpers -------------------------
__device__ __forceinline__ uint32_t smem_u32(const void* p) {
    uint32_t a;
    asm("{ .reg .u64 t; cvta.to.shared.u64 t, %1; cvt.u32.u64 %0, t; }"
        : "=r"(a) : "l"(p));
    return a;
}
__device__ __forceinline__ void cpasync16(uint32_t s, const void* g) {
    asm volatile("cp.async.cg.shared.global [%0], [%1], 16;" :: "r"(s), "l"(g));
}
__device__ __forceinline__ void cp_commit() { asm volatile("cp.async.commit_group;"); }
__device__ __forceinline__ void cp_wait1()  { asm volatile("cp.async.wait_group 1;"); }
__device__ __forceinline__ void cp_wait0()  { asm volatile("cp.async.wait_group 0;"); }
template <int N>
__device__ __forceinline__ void cp_waitn() {
    asm volatile("cp.async.wait_group %0;" :: "n"(N));
}
__device__ __forceinline__ void ldmx4(uint32_t* r, uint32_t addr) {
    asm volatile("ldmatrix.sync.aligned.m8n8.x4.shared.b16 {%0,%1,%2,%3}, [%4];"
                 : "=r"(r[0]), "=r"(r[1]), "=r"(r[2]), "=r"(r[3]) : "r"(addr));
}
__device__ __forceinline__ void ldmx4t(uint32_t* r, uint32_t addr) {
    asm volatile("ldmatrix.sync.aligned.m8n8.x4.trans.shared.b16 {%0,%1,%2,%3}, [%4];"
                 : "=r"(r[0]), "=r"(r[1]), "=r"(r[2]), "=r"(r[3]) : "r"(addr));
}
#define MMA_BF16(d, a, b0_, b1_)                                               \
    asm volatile(                                                              \
        "mma.sync.aligned.m16n8k16.row.col.f32.bf16.bf16.f32 "                 \
        "{%0,%1,%2,%3}, {%4,%5,%6,%7}, {%8,%9}, {%0,%1,%2,%3};"                \
        : "+f"(d[0]), "+f"(d[1]), "+f"(d[2]), "+f"(d[3])                       \
        : "r"(a[0]), "r"(a[1]), "r"(a[2]), "r"(a[3]), "r"(b0_), "r"(b1_))
#define MMA_F16(d, a, b0_, b1_)                                                \
    asm volatile(                                                              \
        "mma.sync.aligned.m16n8k16.row.col.f32.f16.f16.f32 "                   \
        "{%0,%1,%2,%3}, {%4,%5,%6,%7}, {%8,%9}, {%0,%1,%2,%3};"                \
        : "+f"(d[0]), "+f"(d[1]), "+f"(d[2]), "+f"(d[3])                       \
        : "r"(a[0]), "r"(a[1]), "r"(a[2]), "r"(a[3]), "r"(b0_), "r"(b1_))

__device__ __forceinline__ uint16_t bf_bits(__nv_bfloat16 h) {
    return *reinterpret_cast<uint16_t*>(&h);
}
__device__ __forceinline__ void store_split2(__nv_bfloat16* hi, __nv_bfloat16* lo,
                                             int oi, float a, float b) {
    __nv_bfloat16 h0 = __float2bfloat16(a);
    __nv_bfloat16 h1 = __float2bfloat16(b);
    *(__nv_bfloat162*)&hi[oi] = __nv_bfloat162(h0, h1);
    *(__nv_bfloat162*)&lo[oi] = __nv_bfloat162(
        __float2bfloat16(a - __bfloat162float(h0)),
        __float2bfloat16(b - __bfloat162float(h1)));
}
__device__ __forceinline__ void store_split2h(__half* hi, __half* lo,
                                              int oi, float a, float b) {
    __half h0 = __float2half_rn(a);
    __half h1 = __float2half_rn(b);
    *(__half2*)&hi[oi] = __halves2half2(h0, h1);
    *(__half2*)&lo[oi] = __halves2half2(
        __float2half_rn(a - __half2float(h0)),
        __float2half_rn(b - __half2float(h1)));
}

// ---------------------------------------------------------------------------
// Kernel 0a: split x into bf16 hi/lo
// ---------------------------------------------------------------------------
__global__ void split_x(const float* __restrict__ x, int sx)
{
    int i = blockIdx.x * 256 + threadIdx.x;
    if (i >= P_ * PATCH_) return;
    float a = x[clampi(i, sx)];
    __nv_bfloat16 h = __float2bfloat16(a);
    g_X_hi[i] = h;
    g_X_lo[i] = __float2bfloat16(a - __bfloat162float(h));
}

// ---------------------------------------------------------------------------
// Kernel 0b: transpose + split vR_k, vI_k -> 4 bf16 panels [n][k]
// ---------------------------------------------------------------------------
__global__ void split_vk(const float* __restrict__ VR,
                         const float* __restrict__ VI, int sv)
{
    __shared__ float tR[32][33];
    __shared__ float tI[32][33];
    const int tid = threadIdx.x;
    const int n0 = blockIdx.x * 32, k0 = blockIdx.y * 32;

    #pragma unroll
    for (int i = 0; i < 4; i++) {
        int idx = tid + i * 256;
        int kk = idx >> 5, nn = idx & 31;
        int gi = clampi((k0 + kk) * DM + n0 + nn, sv);
        tR[nn][kk] = VR[gi];
        tI[nn][kk] = VI[gi];
    }
    __syncthreads();

    const int kp  = tid & 15;
    const int nn2 = tid >> 4;
    #pragma unroll
    for (int half = 0; half < 2; half++) {
        int n = nn2 + half * 16;
        int k = kp * 2;
        int oi = (n0 + n) * PATCH_ + k0 + k;
        store_split2(g_VtR_hi, g_VtR_lo, oi, tR[n][k], tR[n][k + 1]);
        store_split2(g_VtI_hi, g_VtI_lo, oi, tI[n][k], tI[n][k + 1]);
    }
}

// ---------------------------------------------------------------------------
// Kernel 1: gemm_v via mma.sync, FUSED 3-term split, DEPTH-4 pipeline.
// ---------------------------------------------------------------------------
__global__ void __launch_bounds__(256)
gemm_v_mma(const float* __restrict__ br, const float* __restrict__ bi, int sb)
{
    extern __shared__ __align__(16) char smem[];
    const uint32_t sbase = smem_u32(smem);

    const int tid  = threadIdx.x;
    const int lane = tid & 31, wid = tid >> 5;
    const int g    = lane >> 2, tig = lane & 3;
    const int wm   = wid >> 2, wn = wid & 3;
    const int m0   = blockIdx.y * BM, n0 = blockIdx.x * BN;

    const int a_row_off = (lane & 7) + ((lane >> 3) & 1) * 8;
    const int a_col_off = (lane >> 4) * 8;
    const int b_row_off = (lane & 7) + (lane >> 4) * 8;
    const int b_col_off = ((lane >> 3) & 1) * 8;

    float acc[2][2][2][4] = {};   // [chain][mm][nn][c]

    const int ch_row0 = tid >> 2;
    const int ch_q0   = (tid & 3);
    const int ch_q1   = (tid & 3) + 4;

    auto issue_stage = [&](int t) {
        const int k0 = t * KC;
        const __nv_bfloat16* Gp[6] = {g_X_hi, g_X_lo, g_VtR_hi, g_VtR_lo,
                                      g_VtI_hi, g_VtI_lo};
        const int rowbase[6] = {m0, m0, n0, n0, n0, n0};
        const uint32_t sb_ = sbase + t * VSTAGE;
        #pragma unroll
        for (int p = 0; p < 6; p++) {
            const __nv_bfloat16* gp = Gp[p] + (rowbase[p] + ch_row0) * PATCH_ + k0;
            uint32_t sa = sb_ + p * PANEL + ch_row0 * 144;
            cpasync16(sa + ch_q0 * 16, gp + ch_q0 * 8);
            cpasync16(sa + ch_q1 * 16, gp + ch_q1 * 8);
        }
        cp_commit();
    };

    issue_stage(0);
    issue_stage(1);
    issue_stage(2);
    issue_stage(3);

    #pragma unroll
    for (int t = 0; t < NV_TILES; t++) {
        if      (t == 0) cp_waitn<3>();
        else if (t == 1) cp_waitn<2>();
        else if (t == 2) cp_waitn<1>();
        else             cp_waitn<0>();
        __syncthreads();

        const uint32_t base = sbase + t * VSTAGE;
        #pragma unroll
        for (int kk = 0; kk < KC; kk += 16) {
            uint32_t ah[2][4], al[2][4];
            #pragma unroll
            for (int mm = 0; mm < 2; mm++) {
                int r0 = wm * 32 + mm * 16;
                ldmx4(ah[mm], base + 0 * PANEL + (r0 + a_row_off) * 144 + (kk + a_col_off) * 2);
                ldmx4(al[mm], base + 1 * PANEL + (r0 + a_row_off) * 144 + (kk + a_col_off) * 2);
            }
            #pragma unroll
            for (int c = 0; c < 2; c++) {
                uint32_t bh[4], bl[4];
                int nr = wn * 16;
                ldmx4(bh, base + (2 + c * 2) * PANEL + (nr + b_row_off) * 144 + (kk + b_col_off) * 2);
                ldmx4(bl, base + (3 + c * 2) * PANEL + (nr + b_row_off) * 144 + (kk + b_col_off) * 2);
                #pragma unroll
                for (int mm = 0; mm < 2; mm++)
                    #pragma unroll
                    for (int nn = 0; nn < 2; nn++) {
                        MMA_BF16(acc[c][mm][nn], ah[mm], bh[nn * 2], bh[nn * 2 + 1]);
                        MMA_BF16(acc[c][mm][nn], ah[mm], bl[nn * 2], bl[nn * 2 + 1]);
                        MMA_BF16(acc[c][mm][nn], al[mm], bh[nn * 2], bh[nn * 2 + 1]);
                    }
            }
        }
    }

    // fused epilogue: bias + hi/lo split of vr, vi, vs = vr+vi
    #pragma unroll
    for (int mm = 0; mm < 2; mm++) {
        #pragma unroll
        for (int nn = 0; nn < 2; nn++) {
            int mi = m0 + wm * 32 + mm * 16 + g;
            int ni = n0 + wn * 16 + nn * 8 + tig * 2;
            float b0r = br[clampi(ni, sb)],     b1r = br[clampi(ni + 1, sb)];
            float b0i = bi[clampi(ni, sb)],     b1i = bi[clampi(ni + 1, sb)];
            #pragma unroll
            for (int half = 0; half < 2; half++) {
                int m = mi + half * 8;
                float vr0 = acc[0][mm][nn][half * 2]     + b0r;
                float vr1 = acc[0][mm][nn][half * 2 + 1] + b1r;
                float vi0 = acc[1][mm][nn][half * 2]     + b0i;
                float vi1 = acc[1][mm][nn][half * 2 + 1] + b1i;
                float vs0 = vr0 + vi0, vs1 = vr1 + vi1;
                int oi = m * DM + ni;
                store_split2(g_vr_hi, g_vr_lo, oi, vr0, vr1);
                store_split2(g_vi_hi, g_vi_lo, oi, vi0, vi1);
                store_split2(g_vs_hi, g_vs_lo, oi, vs0, vs1);
            }
        }
    }
}

// ---------------------------------------------------------------------------
// Kernel 2: circulant attention via mma.sync, FUSED split (single K sweep).
// Epilogue writes Y as single fp16 panels (Y16r, Y16i, Y16s).
// ---------------------------------------------------------------------------
__global__ void __launch_bounds__(256)
circ_att_mma(const float* __restrict__ JR, const float* __restrict__ JI, int sj)
{
    extern __shared__ __align__(16) char smem[];
    const uint32_t sbase = smem_u32(smem);
    uint32_t* pair = (uint32_t*)(smem + 2 * CSTAGE);   // [6][512]

    const int tid  = threadIdx.x;
    const int lane = tid & 31, wid = tid >> 5;
    const int g    = lane >> 2, tig = lane & 3;
    const int wm   = wid >> 2, wn = wid & 3;
    const int h    = blockIdx.y;
    const int s0   = blockIdx.x * 64;

    const int bt_row = (lane & 7) + ((lane >> 3) & 1) * 8;
    const int bt_col = (lane >> 4) * 8;

    for (int t = tid; t < 512; t += 256) {
        float jr0 = JR[clampi(((t) & 255) * H_ + h, sj)];
        float jr1 = JR[clampi(((t + 1) & 255) * H_ + h, sj)];
        float ji0 = JI[clampi(((t) & 255) * H_ + h, sj)];
        float ji1 = JI[clampi(((t + 1) & 255) * H_ + h, sj)];
        float v0[3] = {jr0, ji0, jr0 + ji0};
        float v1[3] = {jr1, ji1, jr1 + ji1};
        #pragma unroll
        for (int c = 0; c < 3; c++) {
            __nv_bfloat16 h0 = __float2bfloat16(v0[c]);
            __nv_bfloat16 h1 = __float2bfloat16(v1[c]);
            __nv_bfloat16 l0 = __float2bfloat16(v0[c] - __bfloat162float(h0));
            __nv_bfloat16 l1 = __float2bfloat16(v1[c] - __bfloat162float(h1));
            pair[(c * 2 + 0) * 512 + t] =
                (uint32_t)bf_bits(h0) | ((uint32_t)bf_bits(h1) << 16);
            pair[(c * 2 + 1) * 512 + t] =
                (uint32_t)bf_bits(l0) | ((uint32_t)bf_bits(l1) << 16);
        }
    }

    float acc[3][2][2][4] = {};

    const int ch_row0 = tid >> 2;
    const int ch_q0   = (tid & 3);
    const int ch_q1   = (tid & 3) + 4;

    auto issue_stage = [&](int t) {
        const int k0 = t * KC;
        const __nv_bfloat16* Gp[6] = {g_vr_hi, g_vr_lo, g_vi_hi, g_vi_lo,
                                      g_vs_hi, g_vs_lo};
        const uint32_t sb_ = sbase + (t & 1) * CSTAGE;
        #pragma unroll
        for (int p = 0; p < 6; p++) {
            const __nv_bfloat16* gb = Gp[p] + (k0 + ch_row0) * DM + h * HD;
            uint32_t s = sb_ + p * PANEL + ch_row0 * 144;
            cpasync16(s + ch_q0 * 16, gb + ch_q0 * 8);
            cpasync16(s + ch_q1 * 16, gb + ch_q1 * 8);
        }
        cp_commit();
    };

    __syncthreads();
    issue_stage(0);

    for (int t = 0; t < NC_TILES; t++) {
        const int s = t & 1;
        if (t + 1 < NC_TILES) { issue_stage(t + 1); cp_wait1(); }
        else                  { cp_wait0(); }
        __syncthreads();

        const uint32_t base = sbase + s * CSTAGE;
        #pragma unroll
        for (int kk = 0; kk < KC; kk += 16) {
            const int tbase = s0 + wm * 32 + g + t * 64 + kk + tig * 2;
            #pragma unroll
            for (int c = 0; c < 3; c++) {
                const uint32_t* Ph = &pair[(c * 2 + 0) * 512];
                const uint32_t* Pl = &pair[(c * 2 + 1) * 512];
                uint32_t h0 = Ph[tbase],      h1 = Ph[tbase + 8];
                uint32_t h2 = Ph[tbase + 16], h3 = Ph[tbase + 24];
                uint32_t h4 = Ph[tbase + 32];
                uint32_t l0 = Pl[tbase],      l1 = Pl[tbase + 8];
                uint32_t l2 = Pl[tbase + 16], l3 = Pl[tbase + 24];
                uint32_t l4 = Pl[tbase + 32];
                uint32_t ah0[4] = {h0, h1, h1, h2};
                uint32_t ah1[4] = {h2, h3, h3, h4};
                uint32_t al0[4] = {l0, l1, l1, l2};
                uint32_t al1[4] = {l2, l3, l3, l4};
                uint32_t bh[4], bl[4];
                ldmx4t(bh, base + (c * 2 + 0) * PANEL +
                           (kk + bt_row) * 144 + (wn * 16 + bt_col) * 2);
                ldmx4t(bl, base + (c * 2 + 1) * PANEL +
                           (kk + bt_row) * 144 + (wn * 16 + bt_col) * 2);
                MMA_BF16(acc[c][0][0], ah0, bh[0], bh[1]);
                MMA_BF16(acc[c][0][1], ah0, bh[2], bh[3]);
                MMA_BF16(acc[c][1][0], ah1, bh[0], bh[1]);
                MMA_BF16(acc[c][1][1], ah1, bh[2], bh[3]);
                MMA_BF16(acc[c][0][0], ah0, bl[0], bl[1]);
                MMA_BF16(acc[c][0][1], ah0, bl[2], bl[3]);
                MMA_BF16(acc[c][1][0], ah1, bl[0], bl[1]);
                MMA_BF16(acc[c][1][1], ah1, bl[2], bl[3]);
                MMA_BF16(acc[c][0][0], al0, bh[0], bh[1]);
                MMA_BF16(acc[c][0][1], al0, bh[2], bh[3]);
                MMA_BF16(acc[c][1][0], al1, bh[0], bh[1]);
                MMA_BF16(acc[c][1][1], al1, bh[2], bh[3]);
            }
        }
        __syncthreads();
    }

    // epilogue: Karatsuba combine + single-fp16 write of 3 Y panels
    #pragma unroll
    for (int mm = 0; mm < 2; mm++) {
        #pragma unroll
        for (int nn = 0; nn < 2; nn++) {
            #pragma unroll
            for (int c2 = 0; c2 < 4; c2++) {
                int m = s0 + wm * 32 + mm * 16 + g + (c2 >> 1) * 8;
                int n = h * HD + wn * 16 + nn * 8 + tig * 2 + (c2 & 1);
                float C1 = acc[0][mm][nn][c2];
                float C2 = acc[1][mm][nn][c2];
                float C3 = acc[2][mm][nn][c2];
                float a  = C1 - C2;
                float b  = C3 - C1 - C2;
                int idx = m * DM + n;
                g_Y16r[idx] = __float2half_rn(a);
                g_Y16i[idx] = __float2half_rn(b);
                g_Y16s[idx] = __float2half_rn(a + b);
            }
        }
    }
}

// ---------------------------------------------------------------------------
// Kernel 3: transpose + scale(x64) + fp16 hi/lo split of WR, WI, WR+WI
// ---------------------------------------------------------------------------
__global__ void split_wt(const float* __restrict__ WR,
                         const float* __restrict__ WI, int sw)
{
    __shared__ float tR[32][33];
    __shared__ float tI[32][33];
    const int tid = threadIdx.x;
    const int n0 = blockIdx.x * 32, k0 = blockIdx.y * 32;

    #pragma unroll
    for (int i = 0; i < 4; i++) {
        int idx = tid + i * 256;
        int kk = idx >> 5, nn = idx & 31;
        int gi = clampi((k0 + kk) * DM + n0 + nn, sw);
        tR[nn][kk] = WR[gi];
        tI[nn][kk] = WI[gi];
    }
    __syncthreads();

    const int kp  = tid & 15;
    const int nn2 = tid >> 4;
    #pragma unroll
    for (int half = 0; half < 2; half++) {
        int n = nn2 + half * 16;
        int k = kp * 2;
        float r0 = tR[n][k] * WSCALE,     r1 = tR[n][k + 1] * WSCALE;
        float i0 = tI[n][k] * WSCALE,     i1 = tI[n][k + 1] * WSCALE;
        int oi = (n0 + n) * DM + k0 + k;
        store_split2h(g_W16R_h, g_W16R_l, oi, r0, r1);
        store_split2h(g_W16I_h, g_W16I_l, oi, i0, i1);
        store_split2h(g_W16S_h, g_W16S_l, oi, r0 + i0, r1 + i1);
    }
}

// ---------------------------------------------------------------------------
// Kernel 4: Karatsuba fp16 2-TERM GEMM (A=Y fp16 single, B=W*64 fp16 hi/lo).
//   Per k-step per chain: A*Bh + A*Bl (2 MMA combos). 9 panels / stage.
// ---------------------------------------------------------------------------
__global__ void __launch_bounds__(256)
gemm_out_mma(const float* __restrict__ bR, const float* __restrict__ bI, int sb,
             float* __restrict__ out, int out_floats, int mode)
{
    extern __shared__ __align__(16) char smem[];
    const uint32_t sbase = smem_u32(smem);

    const int tid  = threadIdx.x;
    const int lane = tid & 31, wid = tid >> 5;
    const int g    = lane >> 2, tig = lane & 3;
    const int wm   = wid >> 2, wn = wid & 3;
    const int m0   = blockIdx.y * BM, n0 = blockIdx.x * BN;

    const int a_row_off = (lane & 7) + ((lane >> 3) & 1) * 8;
    const int a_col_off = (lane >> 4) * 8;
    const int b_row_off = (lane & 7) + (lane >> 4) * 8;
    const int b_col_off = ((lane >> 3) & 1) * 8;

    float acc[3][2][2][4] = {};

    const int ch_row0 = tid >> 2;
    const int ch_q0   = (tid & 3);
    const int ch_q1   = (tid & 3) + 4;

    // stage panels: chain c -> c*3+0 Y16 (A), c*3+1 Wh, c*3+2 Wl
    auto issue_stage = [&](int t) {
        const int k0 = t * KC;
        const __half* Gp[9] = {
            g_Y16r, g_W16R_h, g_W16R_l,
            g_Y16i, g_W16I_h, g_W16I_l,
            g_Y16s, g_W16S_h, g_W16S_l};
        const uint32_t sb_ = sbase + (t & 1) * STAGE;
        #pragma unroll
        for (int p = 0; p < 9; p++) {
            const int rowbase = (p % 3 == 0) ? m0 : n0;
            const __half* gp = Gp[p] + (rowbase + ch_row0) * DM + k0;
            uint32_t sa = sb_ + p * PANEL + ch_row0 * 144;
            cpasync16(sa + ch_q0 * 16, gp + ch_q0 * 8);
            cpasync16(sa + ch_q1 * 16, gp + ch_q1 * 8);
        }
        cp_commit();
    };

    issue_stage(0);

    for (int t = 0; t < N_TILES; t++) {
        const int s = t & 1;
        if (t + 1 < N_TILES) { issue_stage(t + 1); cp_wait1(); }
        else                 { cp_wait0(); }
        __syncthreads();

        const uint32_t base = sbase + s * STAGE;
        #pragma unroll
        for (int kk = 0; kk < KC; kk += 16) {
            #pragma unroll
            for (int c = 0; c < 3; c++) {
                uint32_t a[2][4];
                #pragma unroll
                for (int mm = 0; mm < 2; mm++) {
                    int r0 = wm * 32 + mm * 16;
                    ldmx4(a[mm], base + (c * 3 + 0) * PANEL +
                                 (r0 + a_row_off) * 144 + (kk + a_col_off) * 2);
                }
                uint32_t bh[4], bl[4];
                {
                    int nr = wn * 16;
                    ldmx4(bh, base + (c * 3 + 1) * PANEL +
                              (nr + b_row_off) * 144 + (kk + b_col_off) * 2);
                    ldmx4(bl, base + (c * 3 + 2) * PANEL +
                              (nr + b_row_off) * 144 + (kk + b_col_off) * 2);
                }
                #pragma unroll
                for (int mm = 0; mm < 2; mm++)
                    #pragma unroll
                    for (int nn = 0; nn < 2; nn++) {
                        MMA_F16(acc[c][mm][nn], a[mm], bh[nn * 2], bh[nn * 2 + 1]);
                        MMA_F16(acc[c][mm][nn], a[mm], bl[nn * 2], bl[nn * 2 + 1]);
                    }
            }
        }
        __syncthreads();
    }

    const float LN2 = 0.69314718055994531f;
    #pragma unroll
    for (int mm = 0; mm < 2; mm++) {
        #pragma unroll
        for (int nn = 0; nn < 2; nn++) {
            int mi = m0 + wm * 32 + mm * 16 + g;
            int ni = n0 + wn * 16 + nn * 8 + tig * 2;
            #pragma unroll
            for (int c = 0; c < 4; c++) {
                int m = mi + (c >> 1) * 8;
                int n = ni + (c & 1);
                float C1 = acc[0][mm][nn][c];
                float C2 = acc[1][mm][nn][c];
                float C3 = acc[2][mm][nn][c];
                float re = (C1 - C2) * WSCALE_I + bR[clampi(n, sb)];
                float im = (C3 - C1 - C2) * WSCALE_I + bI[clampi(n, sb)];
                float sgn = (__float_as_int(re) < 0) ? -1.0f : 1.0f;
                float a = re * sgn;
                float b = im * sgn;
                float e = __expf(-2.0f * a);
                float s2, c2;
                __sincosf(2.0f * b, &s2, &c2);
                float wr = e * c2, wi = -e * s2;
                float u = 1.0f + wr;
                float res_re = a + 0.5f * __logf(u * u + wi * wi) - LN2;
                if (mode == 0) {
                    int fi = m * DM + n;
                    if (fi < out_floats) out[fi] = res_re;
                } else {
                    float res_im = b + atan2f(wi, u);
                    int fi = (m * DM + n) * 2;
                    if (fi < out_floats)     out[fi]     = res_re;
                    if (fi + 1 < out_floats) out[fi + 1] = res_im;
                }
            }
        }
    }
}

// ---------------------------------------------------------------------------
extern "C" void kernel_launch(void* const* d_in, const int* in_sizes, int n_in,
                              void* d_out, int out_size)
{
    const float* x = nullptr;   int sx = 0;
    const float* vk[2] = {};    int svk = 0;
    const float* J[2]  = {};    int sj = 0;
    const float* wk[2] = {};    int swk = 0;
    const float* bs[4] = {};    int sb = 0;
    int nvk = 0, nj = 0, nwk = 0, nb = 0;

    for (int i = 0; i < n_in; i++) {
        const float* p = (const float*)d_in[i];
        int sz = in_sizes[i];
        if      (sz == 65536   && !x)      { x = p; sx = sz; }
        else if (sz == 524288  && nvk < 2) { vk[nvk++] = p; svk = sz; }
        else if (sz == 8192    && nj  < 2) { J[nj++]   = p; sj  = sz; }
        else if (sz == 4194304 && nwk < 2) { wk[nwk++] = p; swk = sz; }
        else if (sz == 2048    && nb  < 4) { bs[nb++]  = p; sb  = sz; }
    }

    if (!(x && nvk == 2 && nj == 2 && nwk == 2 && nb == 4)) {
        if (n_in < 11) return;
        x     = (const float*)d_in[0];  sx  = in_sizes[0];
        vk[0] = (const float*)d_in[1];  bs[0] = (const float*)d_in[2];
        vk[1] = (const float*)d_in[3];  bs[1] = (const float*)d_in[4];
        J[0]  = (const float*)d_in[5];  J[1]  = (const float*)d_in[6];
        wk[0] = (const float*)d_in[7];  bs[2] = (const float*)d_in[8];
        wk[1] = (const float*)d_in[9];  bs[3] = (const float*)d_in[10];
        svk = in_sizes[1]; sj = in_sizes[5]; swk = in_sizes[7]; sb = in_sizes[2];
    }

    int mode       = (out_size == 2 * P_ * DM) ? 1 : 0;
    int out_floats = out_size;

    static bool attr_done = false;
    static cudaStream_t s_side = nullptr;
    static cudaEvent_t ev_fork = nullptr, ev_join = nullptr;
    if (!attr_done) {
        cudaFuncSetAttribute(gemm_out_mma,
                             cudaFuncAttributeMaxDynamicSharedMemorySize, SMEM_GEMM);
        cudaFuncSetAttribute(gemm_v_mma,
                             cudaFuncAttributeMaxDynamicSharedMemorySize, SMEM_V);
        cudaFuncSetAttribute(circ_att_mma,
                             cudaFuncAttributeMaxDynamicSharedMemorySize, SMEM_C);
        cudaStreamCreateWithFlags(&s_side, cudaStreamNonBlocking);
        cudaEventCreateWithFlags(&ev_fork, cudaEventDisableTiming);
        cudaEventCreateWithFlags(&ev_join, cudaEventDisableTiming);
        attr_done = true;
    }

    // fork: split_wt (independent of the v/att chain) runs on side stream
    cudaEventRecord(ev_fork, 0);
    cudaStreamWaitEvent(s_side, ev_fork, 0);
    split_wt<<<dim3(DM / 32, DM / 32), 256, 0, s_side>>>(wk[0], wk[1], swk);
    cudaEventRecord(ev_join, s_side);

    // main chain (default stream)
    split_x   <<<(P_ * PATCH_ + 255) / 256, 256>>>(x, sx);
    split_vk  <<<dim3(DM / 32, PATCH_ / 32), 256>>>(vk[0], vk[1], svk);
    gemm_v_mma<<<dim3(DM / BN, P_ / BM), 256, SMEM_V>>>(bs[0], bs[1], sb);
    circ_att_mma<<<dim3(P_ / 64, H_), 256, SMEM_C>>>(J[0], J[1], sj);

    // join: gemm_out needs both Y panels (chain) and W panels (side)
    cudaStreamWaitEvent(0, ev_join, 0);
    gemm_out_mma<<<dim3(DM / BN, P_ / BM), 256, SMEM_GEMM>>>(
        bs[2], bs[3], sb, (float*)d_out, out_floats, mode);
}